// round 14
// baseline (speedup 1.0000x reference)
#include <cuda_runtime.h>
#include <cuda_fp16.h>
#include <math.h>
#include <stdint.h>

#define BB 4
#define SS 2048
#define DD 1024
#define HH 16
#define DKK 64
#define NTOT (BB*SS*DD)

// ---------------------------------------------------------------------------
// Scratch (device globals — no allocations allowed)
// ---------------------------------------------------------------------------
__device__ float  g_cs[SS * 32];
__device__ float  g_sn[SS * 32];
__device__ __half g_xh[NTOT];
__device__ __half g_wh[4 * DD * DD];
__device__ __half g_qh[NTOT];
__device__ __half g_kh[NTOT];
__device__ __half g_vh[NTOT];
__device__ __half g_oh[NTOT];

// ---------------------------------------------------------------------------
// mma / ldmatrix / cp.async helpers
// ---------------------------------------------------------------------------
__device__ __forceinline__ void mma_f16(float* c, const unsigned* a, const unsigned* b) {
    asm volatile(
        "mma.sync.aligned.m16n8k16.row.col.f32.f16.f16.f32 "
        "{%0,%1,%2,%3},{%4,%5,%6,%7},{%8,%9},{%0,%1,%2,%3};\n"
        : "+f"(c[0]), "+f"(c[1]), "+f"(c[2]), "+f"(c[3])
        : "r"(a[0]), "r"(a[1]), "r"(a[2]), "r"(a[3]), "r"(b[0]), "r"(b[1]));
}
__device__ __forceinline__ void ldsm4(unsigned* r, uint32_t addr) {
    asm volatile("ldmatrix.sync.aligned.m8n8.x4.shared.b16 {%0,%1,%2,%3}, [%4];"
        : "=r"(r[0]), "=r"(r[1]), "=r"(r[2]), "=r"(r[3]) : "r"(addr));
}
__device__ __forceinline__ void ldsm4t(unsigned* r, uint32_t addr) {
    asm volatile("ldmatrix.sync.aligned.m8n8.x4.trans.shared.b16 {%0,%1,%2,%3}, [%4];"
        : "=r"(r[0]), "=r"(r[1]), "=r"(r[2]), "=r"(r[3]) : "r"(addr));
}
__device__ __forceinline__ void cp16(uint32_t dst, const void* src) {
    asm volatile("cp.async.cg.shared.global [%0], [%1], 16;" :: "r"(dst), "l"(src));
}
__device__ __forceinline__ uint32_t smem_u32(const void* p) {
    uint32_t a;
    asm("{ .reg .u64 t; cvta.to.shared.u64 t, %1; cvt.u32.u64 %0, t; }" : "=r"(a) : "l"(p));
    return a;
}
__device__ __forceinline__ unsigned packh2(float a, float b) {
    __half2 h = __floats2half2_rn(a, b);
    return *(unsigned*)&h;
}
__device__ __forceinline__ float ex2(float x) {
    float y;
    asm("ex2.approx.f32 %0, %1;" : "=f"(y) : "f"(x));
    return y;
}

// ---------------------------------------------------------------------------
// RoPE table (fp64-exact inv_freq)
// ---------------------------------------------------------------------------
__global__ void rope_table(const int* __restrict__ tp) {
    int i = blockIdx.x * blockDim.x + threadIdx.x;
    int s = i >> 5, p = i & 31;
    float pos = (float)tp[s];
    float inv = (float)exp(-(double)p * 0.28782313662425572);
    float ang = pos * inv;
    float sn, cs;
    sincosf(ang, &sn, &cs);
    g_cs[i] = cs;
    g_sn[i] = sn;
}

// ---------------------------------------------------------------------------
// One-shot fp32 -> fp16 conversion: x + 4 weights
// ---------------------------------------------------------------------------
#define NX4 (NTOT/4)
#define NW4 ((DD*DD)/4)
__global__ void conv_all(const float* __restrict__ x,  const float* __restrict__ wq,
                         const float* __restrict__ wk, const float* __restrict__ wv,
                         const float* __restrict__ wo) {
    int i = blockIdx.x * blockDim.x + threadIdx.x;
    const float* src;
    __half* dst;
    int j;
    if (i < NX4) { src = x; dst = g_xh; j = i; }
    else {
        int r = i - NX4;
        int seg = r / NW4;
        j = r - seg * NW4;
        src = (seg == 0) ? wq : (seg == 1) ? wk : (seg == 2) ? wv : wo;
        dst = g_wh + (size_t)seg * DD * DD;
    }
    float4 v = ((const float4*)src)[j];
    ((__half2*)dst)[2 * j]     = __floats2half2_rn(v.x, v.y);
    ((__half2*)dst)[2 * j + 1] = __floats2half2_rn(v.z, v.w);
}

// ---------------------------------------------------------------------------
// GEMM mainloop: single barrier per k-stage.
// ---------------------------------------------------------------------------
#define GSTG 20480
__device__ __forceinline__ void gemm_main(uint32_t smb, const __half* Ag,
                                          const __half* Bg, float acc[4][4][4]) {
    const int t = threadIdx.x;
    const int lane = t & 31, warp = t >> 5;
    const int wm = (warp >> 2) * 64, wn = (warp & 3) * 32;
    const int chunk = t & 3, row0 = t >> 2;
    Ag += chunk * 8;
    Bg += chunk * 8;

    const uint32_t a_off = ((wm + (lane & 15)) * 40 + (lane >> 4) * 8) * 2;
    const int br = lane & 7, bg = lane >> 3;
    const uint32_t b_off = ((wn + br + (bg >> 1) * 8) * 40 + (bg & 1) * 8) * 2;

#pragma unroll
    for (int ps = 0; ps < 3; ps++) {
        uint32_t sb = smb + ps * GSTG;
        const __half* ga = Ag + ps * 32;
        const __half* gb = Bg + ps * 32;
#pragma unroll
        for (int j = 0; j < 2; j++) {
            int row = row0 + j * 64;
            cp16(sb + row * 80 + chunk * 16, ga + (size_t)row * DD);
            cp16(sb + 128 * 80 + row * 80 + chunk * 16, gb + (size_t)row * DD);
        }
        asm volatile("cp.async.commit_group;");
    }

    for (int s = 0; s < 32; s++) {
        asm volatile("cp.async.wait_group 2;");
        __syncthreads();
        const uint32_t sA = smb + (s & 3) * GSTG;
        const uint32_t sB = sA + 128 * 80;
#pragma unroll
        for (int ks = 0; ks < 2; ks++) {
            unsigned af[4][4], bf[2][4];
#pragma unroll
            for (int mt = 0; mt < 4; mt++)
                ldsm4(af[mt], sA + a_off + mt * (16 * 80) + ks * 32);
#pragma unroll
            for (int np = 0; np < 2; np++)
                ldsm4(bf[np], sB + b_off + np * (16 * 80) + ks * 32);
#pragma unroll
            for (int mt = 0; mt < 4; mt++)
#pragma unroll
                for (int nt = 0; nt < 4; nt++)
                    mma_f16(acc[mt][nt], af[mt], &bf[nt >> 1][(nt & 1) * 2]);
        }
        if (s + 3 < 32) {
            uint32_t sb = smb + ((s + 3) & 3) * GSTG;
            const __half* ga = Ag + (s + 3) * 32;
            const __half* gb = Bg + (s + 3) * 32;
#pragma unroll
            for (int j = 0; j < 2; j++) {
                int row = row0 + j * 64;
                cp16(sb + row * 80 + chunk * 16, ga + (size_t)row * DD);
                cp16(sb + 128 * 80 + row * 80 + chunk * 16, gb + (size_t)row * DD);
            }
        }
        asm volatile("cp.async.commit_group;");
    }
}

// ---------------------------------------------------------------------------
// Fused QKV GEMM + RoPE epilogue. Q scale 0.125*log2(e) (exp2 softmax).
// ---------------------------------------------------------------------------
#define QSCALE 0.1803368801111204f   // 0.125 * log2(e)
__global__ __launch_bounds__(256) void gemm_qkv() {
    extern __shared__ __align__(128) char smem[];
    const uint32_t smb = smem_u32(smem);
    const int t = threadIdx.x;
    const int lane = t & 31, warp = t >> 5;
    const int qr = lane >> 2, ql = lane & 3;
    const int wm = (warp >> 2) * 64, wn = (warp & 3) * 32;
    const int w  = blockIdx.x >> 3;
    const int bn = (blockIdx.x & 7) * 128;
    const int bm = blockIdx.y * 128;

    float acc[4][4][4] = {};
    gemm_main(smb, g_xh + (size_t)bm * DD, g_wh + (size_t)w * DD * DD + (size_t)bn * DD, acc);

    const int r0 = bm + wm + qr;
    const int c0 = bn + wn + 2 * ql;
    if (w == 2) {
#pragma unroll
        for (int mt = 0; mt < 4; mt++)
#pragma unroll
            for (int nt = 0; nt < 4; nt++) {
                __half* vp = g_vh + (size_t)(r0 + mt * 16) * DD + c0 + nt * 8;
                *(__half2*)vp = __floats2half2_rn(acc[mt][nt][0], acc[mt][nt][1]);
                *(__half2*)(vp + 8 * DD) = __floats2half2_rn(acc[mt][nt][2], acc[mt][nt][3]);
            }
    } else {
        __half* dst = (w == 0) ? g_qh : g_kh;
        const float sc = (w == 0) ? QSCALE : 1.0f;
#pragma unroll
        for (int mt = 0; mt < 4; mt++) {
            int rA = r0 + mt * 16;
            int rB = rA + 8;
            int sA = rA & (SS - 1), sB = rB & (SS - 1);
#pragma unroll
            for (int nt = 0; nt < 4; nt++) {
                int cc = c0 + nt * 8;
                int p = (cc & 63) >> 1;
                float csA = g_cs[sA * 32 + p], snA = g_sn[sA * 32 + p];
                float csB = g_cs[sB * 32 + p], snB = g_sn[sB * 32 + p];
                float a0 = acc[mt][nt][0], a1 = acc[mt][nt][1];
                float b0 = acc[mt][nt][2], b1 = acc[mt][nt][3];
                __half* dp = dst + (size_t)rA * DD + cc;
                *(__half2*)dp = __floats2half2_rn((a0 * csA - a1 * snA) * sc,
                                                  (a0 * snA + a1 * csA) * sc);
                *(__half2*)(dp + 8 * DD) = __floats2half2_rn((b0 * csB - b1 * snB) * sc,
                                                             (b0 * snB + b1 * csB) * sc);
            }
        }
    }
}

// ---------------------------------------------------------------------------
// Output projection GEMM
// ---------------------------------------------------------------------------
__global__ __launch_bounds__(256) void gemm_out(float* __restrict__ C) {
    extern __shared__ __align__(128) char smem[];
    const uint32_t smb = smem_u32(smem);
    const int t = threadIdx.x;
    const int lane = t & 31, warp = t >> 5;
    const int qr = lane >> 2, ql = lane & 3;
    const int wm = (warp >> 2) * 64, wn = (warp & 3) * 32;
    const int bn = blockIdx.x * 128;
    const int bm = blockIdx.y * 128;

    float acc[4][4][4] = {};
    gemm_main(smb, g_oh + (size_t)bm * DD, g_wh + (size_t)3 * DD * DD + (size_t)bn * DD, acc);

    const int r0 = bm + wm + qr;
    const int c0 = bn + wn + 2 * ql;
#pragma unroll
    for (int mt = 0; mt < 4; mt++)
#pragma unroll
        for (int nt = 0; nt < 4; nt++) {
            float* cp = C + (size_t)(r0 + mt * 16) * DD + c0 + nt * 8;
            *(float2*)cp = make_float2(acc[mt][nt][0], acc[mt][nt][1]);
            *(float2*)(cp + 8 * DD) = make_float2(acc[mt][nt][2], acc[mt][nt][3]);
        }
}

// ---------------------------------------------------------------------------
// fp16 flash attention v7: R13 base + Q-fragments resident in registers
// (loaded once, reused all k-tiles) + masked-warp skip on the 2nd diagonal
// tile. Single q-tile per block, largest-first dispatch.
// ---------------------------------------------------------------------------
#define HPAD 72
#define QT_B  (0)
#define KT_B(s) (128 * HPAD * 2 + (s) * (2 * 64 * HPAD * 2))
#define VT_B(s) (KT_B(s) + 64 * HPAD * 2)
#define ATTN_SMEM_B (128 * HPAD * 2 + 6 * 64 * HPAD * 2)   // 73728

__global__ __launch_bounds__(256) void attn_h() {
    extern __shared__ __align__(16) __half smh[];
    const uint32_t u0 = smem_u32(smh);
    __half* Qs = smh;

    const int h = blockIdx.y, b = blockIdx.z;
    const int t = threadIdx.x;
    const int lane = t & 31, warp = t >> 5;
    const int qr = lane >> 2, ql = lane & 3;
    const int br = lane & 7, bg = lane >> 3;

    const uint32_t offA  = ((warp * 16 + (lane & 15)) * HPAD + (lane >> 4) * 8) * 2;
    const uint32_t offBk = ((br + (bg >> 1) * 8) * HPAD + (bg & 1) * 8) * 2;
    const uint32_t offBv = ((br + (bg & 1) * 8) * HPAD + (bg >> 1) * 8) * 2;

#define AKLOAD(kt_, buf_) do {                                                      \
        const __half* kb_ = g_kh + ((size_t)b * SS + (size_t)(kt_) * 64) * DD + h * DKK; \
        const __half* vb_ = g_vh + ((size_t)b * SS + (size_t)(kt_) * 64) * DD + h * DKK; \
        uint32_t kd_ = u0 + KT_B(buf_), vd_ = u0 + VT_B(buf_);                      \
        _Pragma("unroll")                                                           \
        for (int i_ = 0; i_ < 2; i_++) {                                            \
            int idx_ = t + i_ * 256;                                                \
            int r_ = idx_ >> 3, cb_ = (idx_ & 7) * 16;                              \
            cp16(kd_ + r_ * (HPAD * 2) + cb_, kb_ + (size_t)r_ * DD + (idx_ & 7) * 8); \
            cp16(vd_ + r_ * (HPAD * 2) + cb_, vb_ + (size_t)r_ * DD + (idx_ & 7) * 8); \
        }                                                                           \
    } while (0)

    const int qt = 15 - (int)blockIdx.x;   // largest q-tile first
    const int nk = 2 * qt + 2;

    // load Q tile: 128 rows x 64 halves
    const __half* qb = g_qh + ((size_t)b * SS + (size_t)qt * 128) * DD + h * DKK;
#pragma unroll
    for (int i = 0; i < 4; i++) {
        int idx = t + i * 256;
        int r = idx >> 3, c = (idx & 7) * 8;
        *(uint4*)&Qs[r * HPAD + c] = *(const uint4*)&qb[(size_t)r * DD + c];
    }

    // kick off K/V prefetch before the Q barrier
    AKLOAD(0, 0);
    asm volatile("cp.async.commit_group;");
    AKLOAD(1, 1);
    asm volatile("cp.async.commit_group;");

    __syncthreads();   // Q stores visible

    // ---- Q fragments resident in registers for the whole k-loop ----
    unsigned qa[4][4];
#pragma unroll
    for (int ks = 0; ks < 4; ks++)
        ldsm4(qa[ks], u0 + QT_B + offA + ks * 32);

    float o[8][4] = {};
    float l0 = 0.0f, l1 = 0.0f;

    int buf = 0;
    for (int kt = 0; kt < nk; kt++) {
        asm volatile("cp.async.wait_group 1;");
        __syncthreads();

        const uint32_t u_k = u0 + KT_B(buf);
        const uint32_t u_v = u0 + VT_B(buf);
        buf = (buf == 2) ? 0 : buf + 1;

        // warps 0-3 fully masked on the 2nd diagonal tile -> skip (exact no-op)
        if (!(kt == 2 * qt + 1 && warp < 4)) {
            // ---- S = Q K^T (log2-scaled) ----
            float sv[8][4] = {};
#pragma unroll
            for (int ks = 0; ks < 4; ks++) {
#pragma unroll
                for (int np = 0; np < 4; np++) {
                    unsigned bf[4];
                    ldsm4(bf, u_k + offBk + np * (16 * HPAD * 2) + ks * 32);
                    mma_f16(sv[2 * np],     qa[ks], &bf[0]);
                    mma_f16(sv[2 * np + 1], qa[ks], &bf[2]);
                }
            }

            // ---- causal mask (diagonal spans k-tiles 2qt and 2qt+1) ----
            if (kt >= 2 * qt) {
                const int off = (kt - 2 * qt) * 64;
                const int r_lo = warp * 16 + qr - off, r_hi = r_lo + 8;
#pragma unroll
                for (int nt = 0; nt < 8; nt++) {
                    int c0 = nt * 8 + 2 * ql, c1 = c0 + 1;
                    if (c0 > r_lo) sv[nt][0] = -1e30f;
                    if (c1 > r_lo) sv[nt][1] = -1e30f;
                    if (c0 > r_hi) sv[nt][2] = -1e30f;
                    if (c1 > r_hi) sv[nt][3] = -1e30f;
                }
            }

            // ---- no-max softmax: P = exp2(s) ----
            float rs0 = 0.0f, rs1 = 0.0f;
#pragma unroll
            for (int nt = 0; nt < 8; nt++) {
                sv[nt][0] = ex2(sv[nt][0]);
                sv[nt][1] = ex2(sv[nt][1]);
                sv[nt][2] = ex2(sv[nt][2]);
                sv[nt][3] = ex2(sv[nt][3]);
                rs0 += sv[nt][0] + sv[nt][1];
                rs1 += sv[nt][2] + sv[nt][3];
            }
            l0 += rs0;
            l1 += rs1;

            // ---- P fragments directly in registers ----
            unsigned pa[4][4];
#pragma unroll
            for (int ks = 0; ks < 4; ks++) {
                pa[ks][0] = packh2(sv[2 * ks][0],     sv[2 * ks][1]);
                pa[ks][1] = packh2(sv[2 * ks][2],     sv[2 * ks][3]);
                pa[ks][2] = packh2(sv[2 * ks + 1][0], sv[2 * ks + 1][1]);
                pa[ks][3] = packh2(sv[2 * ks + 1][2], sv[2 * ks + 1][3]);
            }

            // ---- O += P V  (V row-major via ldmatrix.trans) ----
#pragma unroll
            for (int ks = 0; ks < 4; ks++) {
#pragma unroll
                for (int np = 0; np < 4; np++) {
                    unsigned bf[4];
                    ldsm4t(bf, u_v + offBv + ks * (16 * HPAD * 2) + np * 32);
                    mma_f16(o[2 * np],     pa[ks], &bf[0]);
                    mma_f16(o[2 * np + 1], pa[ks], &bf[2]);
                }
            }
        }

        // prefetch k-tile kt+2 into ring slot
        if (kt + 2 < nk) AKLOAD(kt + 2, (kt + 2) % 3);
        asm volatile("cp.async.commit_group;");
    }

    // ---- row-sum reduce across quad lanes, then epilogue ----
    l0 += __shfl_xor_sync(0xffffffffu, l0, 1);
    l0 += __shfl_xor_sync(0xffffffffu, l0, 2);
    l1 += __shfl_xor_sync(0xffffffffu, l1, 1);
    l1 += __shfl_xor_sync(0xffffffffu, l1, 2);

    const float inv0 = 1.0f / l0, inv1 = 1.0f / l1;
    __half* ob = g_oh + ((size_t)b * SS + (size_t)qt * 128 + warp * 16 + qr) * DD + h * DKK;
#pragma unroll
    for (int nt = 0; nt < 8; nt++) {
        int c0 = nt * 8 + 2 * ql;
        *(__half2*)&ob[c0] = __floats2half2_rn(o[nt][0] * inv0, o[nt][1] * inv0);
        *(__half2*)&ob[(size_t)8 * DD + c0] = __floats2half2_rn(o[nt][2] * inv1, o[nt][3] * inv1);
    }
#undef AKLOAD
}

// ---------------------------------------------------------------------------
extern "C" void kernel_launch(void* const* d_in, const int* in_sizes, int n_in,
                              void* d_out, int out_size) {
    const float* x  = (const float*)d_in[0];
    const float* wq = (const float*)d_in[1];
    const float* wk = (const float*)d_in[2];
    const float* wv = (const float*)d_in[3];
    const float* wo = (const float*)d_in[4];
    const int*   tp = (const int*)d_in[5];
    float* out = (float*)d_out;

    rope_table<<<(SS * 32) / 256, 256>>>(tp);
    conv_all<<<(NX4 + 4 * NW4) / 256, 256>>>(x, wq, wk, wv, wo);

    const int GEMM_SMEM = 4 * GSTG;          // 81920 B
    cudaFuncSetAttribute(gemm_qkv, cudaFuncAttributeMaxDynamicSharedMemorySize, GEMM_SMEM);
    cudaFuncSetAttribute(gemm_out, cudaFuncAttributeMaxDynamicSharedMemorySize, GEMM_SMEM);

    gemm_qkv<<<dim3(24, (BB * SS) / 128), 256, GEMM_SMEM>>>();

    cudaFuncSetAttribute(attn_h, cudaFuncAttributeMaxDynamicSharedMemorySize, ATTN_SMEM_B);
    attn_h<<<dim3(16, HH, BB), 256, ATTN_SMEM_B>>>();

    gemm_out<<<dim3(DD / 128, (BB * SS) / 128), 256, GEMM_SMEM>>>(out);
}

// round 15
// speedup vs baseline: 1.0367x; 1.0367x over previous
#include <cuda_runtime.h>
#include <cuda_fp16.h>
#include <math.h>
#include <stdint.h>

#define BB 4
#define SS 2048
#define DD 1024
#define HH 16
#define DKK 64
#define NTOT (BB*SS*DD)

// ---------------------------------------------------------------------------
// Scratch (device globals — no allocations allowed)
// ---------------------------------------------------------------------------
__device__ float  g_cs[SS * 32];
__device__ float  g_sn[SS * 32];
__device__ __half g_xh[NTOT];
__device__ __half g_wh[4 * DD * DD];
__device__ __half g_qh[NTOT];
__device__ __half g_kh[NTOT];
__device__ __half g_vh[NTOT];
__device__ __half g_oh[NTOT];

// ---------------------------------------------------------------------------
// mma / ldmatrix / cp.async helpers
// ---------------------------------------------------------------------------
__device__ __forceinline__ void mma_f16(float* c, const unsigned* a, const unsigned* b) {
    asm volatile(
        "mma.sync.aligned.m16n8k16.row.col.f32.f16.f16.f32 "
        "{%0,%1,%2,%3},{%4,%5,%6,%7},{%8,%9},{%0,%1,%2,%3};\n"
        : "+f"(c[0]), "+f"(c[1]), "+f"(c[2]), "+f"(c[3])
        : "r"(a[0]), "r"(a[1]), "r"(a[2]), "r"(a[3]), "r"(b[0]), "r"(b[1]));
}
__device__ __forceinline__ void ldsm4(unsigned* r, uint32_t addr) {
    asm volatile("ldmatrix.sync.aligned.m8n8.x4.shared.b16 {%0,%1,%2,%3}, [%4];"
        : "=r"(r[0]), "=r"(r[1]), "=r"(r[2]), "=r"(r[3]) : "r"(addr));
}
__device__ __forceinline__ void ldsm4t(unsigned* r, uint32_t addr) {
    asm volatile("ldmatrix.sync.aligned.m8n8.x4.trans.shared.b16 {%0,%1,%2,%3}, [%4];"
        : "=r"(r[0]), "=r"(r[1]), "=r"(r[2]), "=r"(r[3]) : "r"(addr));
}
__device__ __forceinline__ void cp16(uint32_t dst, const void* src) {
    asm volatile("cp.async.cg.shared.global [%0], [%1], 16;" :: "r"(dst), "l"(src));
}
__device__ __forceinline__ uint32_t smem_u32(const void* p) {
    uint32_t a;
    asm("{ .reg .u64 t; cvta.to.shared.u64 t, %1; cvt.u32.u64 %0, t; }" : "=r"(a) : "l"(p));
    return a;
}
__device__ __forceinline__ unsigned packh2(float a, float b) {
    __half2 h = __floats2half2_rn(a, b);
    return *(unsigned*)&h;
}
__device__ __forceinline__ float ex2(float x) {
    float y;
    asm("ex2.approx.f32 %0, %1;" : "=f"(y) : "f"(x));
    return y;
}

// ---------------------------------------------------------------------------
// Fused prep: RoPE table (blocks [0,256)) + fp32->fp16 conversion of x and
// all 4 weights (remaining blocks). The two halves are independent; both
// complete before gemm_qkv launches.
// ---------------------------------------------------------------------------
#define NX4 (NTOT/4)
#define NW4 ((DD*DD)/4)
#define TBLK 256   // (SS*32)/256 blocks of table work
__global__ void prep_all(const int* __restrict__ tp,
                         const float* __restrict__ x,  const float* __restrict__ wq,
                         const float* __restrict__ wk, const float* __restrict__ wv,
                         const float* __restrict__ wo) {
    if (blockIdx.x < TBLK) {
        int i = blockIdx.x * blockDim.x + threadIdx.x;   // 0 .. SS*32
        int s = i >> 5, p = i & 31;
        float pos = (float)tp[s];
        float inv = (float)exp(-(double)p * 0.28782313662425572);
        float ang = pos * inv;
        float sn, cs;
        sincosf(ang, &sn, &cs);
        g_cs[i] = cs;
        g_sn[i] = sn;
        return;
    }
    int i = (blockIdx.x - TBLK) * blockDim.x + threadIdx.x;
    const float* src;
    __half* dst;
    int j;
    if (i < NX4) { src = x; dst = g_xh; j = i; }
    else {
        int r = i - NX4;
        int seg = r / NW4;
        j = r - seg * NW4;
        src = (seg == 0) ? wq : (seg == 1) ? wk : (seg == 2) ? wv : wo;
        dst = g_wh + (size_t)seg * DD * DD;
    }
    float4 v = ((const float4*)src)[j];
    ((__half2*)dst)[2 * j]     = __floats2half2_rn(v.x, v.y);
    ((__half2*)dst)[2 * j + 1] = __floats2half2_rn(v.z, v.w);
}

// ---------------------------------------------------------------------------
// GEMM mainloop: single barrier per k-stage.
// ---------------------------------------------------------------------------
#define GSTG 20480
__device__ __forceinline__ void gemm_main(uint32_t smb, const __half* Ag,
                                          const __half* Bg, float acc[4][4][4]) {
    const int t = threadIdx.x;
    const int lane = t & 31, warp = t >> 5;
    const int wm = (warp >> 2) * 64, wn = (warp & 3) * 32;
    const int chunk = t & 3, row0 = t >> 2;
    Ag += chunk * 8;
    Bg += chunk * 8;

    const uint32_t a_off = ((wm + (lane & 15)) * 40 + (lane >> 4) * 8) * 2;
    const int br = lane & 7, bg = lane >> 3;
    const uint32_t b_off = ((wn + br + (bg >> 1) * 8) * 40 + (bg & 1) * 8) * 2;

#pragma unroll
    for (int ps = 0; ps < 3; ps++) {
        uint32_t sb = smb + ps * GSTG;
        const __half* ga = Ag + ps * 32;
        const __half* gb = Bg + ps * 32;
#pragma unroll
        for (int j = 0; j < 2; j++) {
            int row = row0 + j * 64;
            cp16(sb + row * 80 + chunk * 16, ga + (size_t)row * DD);
            cp16(sb + 128 * 80 + row * 80 + chunk * 16, gb + (size_t)row * DD);
        }
        asm volatile("cp.async.commit_group;");
    }

    for (int s = 0; s < 32; s++) {
        asm volatile("cp.async.wait_group 2;");
        __syncthreads();
        const uint32_t sA = smb + (s & 3) * GSTG;
        const uint32_t sB = sA + 128 * 80;
#pragma unroll
        for (int ks = 0; ks < 2; ks++) {
            unsigned af[4][4], bf[2][4];
#pragma unroll
            for (int mt = 0; mt < 4; mt++)
                ldsm4(af[mt], sA + a_off + mt * (16 * 80) + ks * 32);
#pragma unroll
            for (int np = 0; np < 2; np++)
                ldsm4(bf[np], sB + b_off + np * (16 * 80) + ks * 32);
#pragma unroll
            for (int mt = 0; mt < 4; mt++)
#pragma unroll
                for (int nt = 0; nt < 4; nt++)
                    mma_f16(acc[mt][nt], af[mt], &bf[nt >> 1][(nt & 1) * 2]);
        }
        if (s + 3 < 32) {
            uint32_t sb = smb + ((s + 3) & 3) * GSTG;
            const __half* ga = Ag + (s + 3) * 32;
            const __half* gb = Bg + (s + 3) * 32;
#pragma unroll
            for (int j = 0; j < 2; j++) {
                int row = row0 + j * 64;
                cp16(sb + row * 80 + chunk * 16, ga + (size_t)row * DD);
                cp16(sb + 128 * 80 + row * 80 + chunk * 16, gb + (size_t)row * DD);
            }
        }
        asm volatile("cp.async.commit_group;");
    }
}

// ---------------------------------------------------------------------------
// Fused QKV GEMM + RoPE epilogue. Q scale 0.125*log2(e) (exp2 softmax).
// ---------------------------------------------------------------------------
#define QSCALE 0.1803368801111204f   // 0.125 * log2(e)
__global__ __launch_bounds__(256) void gemm_qkv() {
    extern __shared__ __align__(128) char smem[];
    const uint32_t smb = smem_u32(smem);
    const int t = threadIdx.x;
    const int lane = t & 31, warp = t >> 5;
    const int qr = lane >> 2, ql = lane & 3;
    const int wm = (warp >> 2) * 64, wn = (warp & 3) * 32;
    const int w  = blockIdx.x >> 3;
    const int bn = (blockIdx.x & 7) * 128;
    const int bm = blockIdx.y * 128;

    float acc[4][4][4] = {};
    gemm_main(smb, g_xh + (size_t)bm * DD, g_wh + (size_t)w * DD * DD + (size_t)bn * DD, acc);

    const int r0 = bm + wm + qr;
    const int c0 = bn + wn + 2 * ql;
    if (w == 2) {
#pragma unroll
        for (int mt = 0; mt < 4; mt++)
#pragma unroll
            for (int nt = 0; nt < 4; nt++) {
                __half* vp = g_vh + (size_t)(r0 + mt * 16) * DD + c0 + nt * 8;
                *(__half2*)vp = __floats2half2_rn(acc[mt][nt][0], acc[mt][nt][1]);
                *(__half2*)(vp + 8 * DD) = __floats2half2_rn(acc[mt][nt][2], acc[mt][nt][3]);
            }
    } else {
        __half* dst = (w == 0) ? g_qh : g_kh;
        const float sc = (w == 0) ? QSCALE : 1.0f;
#pragma unroll
        for (int mt = 0; mt < 4; mt++) {
            int rA = r0 + mt * 16;
            int rB = rA + 8;
            int sA = rA & (SS - 1), sB = rB & (SS - 1);
#pragma unroll
            for (int nt = 0; nt < 4; nt++) {
                int cc = c0 + nt * 8;
                int p = (cc & 63) >> 1;
                float csA = g_cs[sA * 32 + p], snA = g_sn[sA * 32 + p];
                float csB = g_cs[sB * 32 + p], snB = g_sn[sB * 32 + p];
                float a0 = acc[mt][nt][0], a1 = acc[mt][nt][1];
                float b0 = acc[mt][nt][2], b1 = acc[mt][nt][3];
                __half* dp = dst + (size_t)rA * DD + cc;
                *(__half2*)dp = __floats2half2_rn((a0 * csA - a1 * snA) * sc,
                                                  (a0 * snA + a1 * csA) * sc);
                *(__half2*)(dp + 8 * DD) = __floats2half2_rn((b0 * csB - b1 * snB) * sc,
                                                             (b0 * snB + b1 * csB) * sc);
            }
        }
    }
}

// ---------------------------------------------------------------------------
// Output projection GEMM
// ---------------------------------------------------------------------------
__global__ __launch_bounds__(256) void gemm_out(float* __restrict__ C) {
    extern __shared__ __align__(128) char smem[];
    const uint32_t smb = smem_u32(smem);
    const int t = threadIdx.x;
    const int lane = t & 31, warp = t >> 5;
    const int qr = lane >> 2, ql = lane & 3;
    const int wm = (warp >> 2) * 64, wn = (warp & 3) * 32;
    const int bn = blockIdx.x * 128;
    const int bm = blockIdx.y * 128;

    float acc[4][4][4] = {};
    gemm_main(smb, g_oh + (size_t)bm * DD, g_wh + (size_t)3 * DD * DD + (size_t)bn * DD, acc);

    const int r0 = bm + wm + qr;
    const int c0 = bn + wn + 2 * ql;
#pragma unroll
    for (int mt = 0; mt < 4; mt++)
#pragma unroll
        for (int nt = 0; nt < 4; nt++) {
            float* cp = C + (size_t)(r0 + mt * 16) * DD + c0 + nt * 8;
            *(float2*)cp = make_float2(acc[mt][nt][0], acc[mt][nt][1]);
            *(float2*)(cp + 8 * DD) = make_float2(acc[mt][nt][2], acc[mt][nt][3]);
        }
}

// ---------------------------------------------------------------------------
// fp16 flash attention v4 (exact R10 configuration — measured optimum):
// no-max softmax (P = exp2(s) directly), q-tile 128 (8 warps), k-tile 64,
// P in registers, 3-stage cp.async ring, 1 barrier/k-tile, balanced pairing
// (block bx -> q-tiles 15-bx then bx).
// ---------------------------------------------------------------------------
#define HPAD 72
#define QT_B  (0)
#define KT_B(s) (128 * HPAD * 2 + (s) * (2 * 64 * HPAD * 2))
#define VT_B(s) (KT_B(s) + 64 * HPAD * 2)
#define ATTN_SMEM_B (128 * HPAD * 2 + 6 * 64 * HPAD * 2)   // 73728

__global__ __launch_bounds__(256) void attn_h() {
    extern __shared__ __align__(16) __half smh[];
    const uint32_t u0 = smem_u32(smh);
    __half* Qs = smh;

    const int h = blockIdx.y, b = blockIdx.z;
    const int t = threadIdx.x;
    const int lane = t & 31, warp = t >> 5;
    const int qr = lane >> 2, ql = lane & 3;
    const int br = lane & 7, bg = lane >> 3;

    const uint32_t offA  = ((warp * 16 + (lane & 15)) * HPAD + (lane >> 4) * 8) * 2;
    const uint32_t offBk = ((br + (bg >> 1) * 8) * HPAD + (bg & 1) * 8) * 2;
    const uint32_t offBv = ((br + (bg & 1) * 8) * HPAD + (bg >> 1) * 8) * 2;

#define AKLOAD(kt_, buf_) do {                                                      \
        const __half* kb_ = g_kh + ((size_t)b * SS + (size_t)(kt_) * 64) * DD + h * DKK; \
        const __half* vb_ = g_vh + ((size_t)b * SS + (size_t)(kt_) * 64) * DD + h * DKK; \
        uint32_t kd_ = u0 + KT_B(buf_), vd_ = u0 + VT_B(buf_);                      \
        _Pragma("unroll")                                                           \
        for (int i_ = 0; i_ < 2; i_++) {                                            \
            int idx_ = t + i_ * 256;                                                \
            int r_ = idx_ >> 3, cb_ = (idx_ & 7) * 16;                              \
            cp16(kd_ + r_ * (HPAD * 2) + cb_, kb_ + (size_t)r_ * DD + (idx_ & 7) * 8); \
            cp16(vd_ + r_ * (HPAD * 2) + cb_, vb_ + (size_t)r_ * DD + (idx_ & 7) * 8); \
        }                                                                           \
    } while (0)

#pragma unroll
    for (int pass = 0; pass < 2; pass++) {
        const int qt = pass ? blockIdx.x : 15 - blockIdx.x;   // q-tile of 128 rows
        const int nk = 2 * qt + 2;

        // load Q tile: 128 rows x 64 halves
        const __half* qb = g_qh + ((size_t)b * SS + (size_t)qt * 128) * DD + h * DKK;
#pragma unroll
        for (int i = 0; i < 4; i++) {
            int idx = t + i * 256;
            int r = idx >> 3, c = (idx & 7) * 8;
            *(uint4*)&Qs[r * HPAD + c] = *(const uint4*)&qb[(size_t)r * DD + c];
        }

        float o[8][4] = {};
        float l0 = 0.0f, l1 = 0.0f;

        AKLOAD(0, 0);
        asm volatile("cp.async.commit_group;");
        AKLOAD(1, 1);
        asm volatile("cp.async.commit_group;");

        int buf = 0;
        for (int kt = 0; kt < nk; kt++) {
            asm volatile("cp.async.wait_group 1;");
            __syncthreads();

            const uint32_t u_k = u0 + KT_B(buf);
            const uint32_t u_v = u0 + VT_B(buf);
            buf = (buf == 2) ? 0 : buf + 1;

            // ---- S = Q K^T (log2-scaled) ----
            float sv[8][4] = {};
#pragma unroll
            for (int ks = 0; ks < 4; ks++) {
                unsigned a[4];
                ldsm4(a, u0 + QT_B + offA + ks * 32);
#pragma unroll
                for (int np = 0; np < 4; np++) {
                    unsigned bf[4];
                    ldsm4(bf, u_k + offBk + np * (16 * HPAD * 2) + ks * 32);
                    mma_f16(sv[2 * np],     a, &bf[0]);
                    mma_f16(sv[2 * np + 1], a, &bf[2]);
                }
            }

            // ---- causal mask (diagonal spans k-tiles 2qt and 2qt+1) ----
            if (kt >= 2 * qt) {
                const int off = (kt - 2 * qt) * 64;
                const int r_lo = warp * 16 + qr - off, r_hi = r_lo + 8;
#pragma unroll
                for (int nt = 0; nt < 8; nt++) {
                    int c0 = nt * 8 + 2 * ql, c1 = c0 + 1;
                    if (c0 > r_lo) sv[nt][0] = -1e30f;
                    if (c1 > r_lo) sv[nt][1] = -1e30f;
                    if (c0 > r_hi) sv[nt][2] = -1e30f;
                    if (c1 > r_hi) sv[nt][3] = -1e30f;
                }
            }

            // ---- no-max softmax: P = exp2(s) ----
            float rs0 = 0.0f, rs1 = 0.0f;
#pragma unroll
            for (int nt = 0; nt < 8; nt++) {
                sv[nt][0] = ex2(sv[nt][0]);
                sv[nt][1] = ex2(sv[nt][1]);
                sv[nt][2] = ex2(sv[nt][2]);
                sv[nt][3] = ex2(sv[nt][3]);
                rs0 += sv[nt][0] + sv[nt][1];
                rs1 += sv[nt][2] + sv[nt][3];
            }
            l0 += rs0;
            l1 += rs1;

            // ---- P fragments directly in registers (C-layout == A-layout) ----
            unsigned pa[4][4];
#pragma unroll
            for (int ks = 0; ks < 4; ks++) {
                pa[ks][0] = packh2(sv[2 * ks][0],     sv[2 * ks][1]);
                pa[ks][1] = packh2(sv[2 * ks][2],     sv[2 * ks][3]);
                pa[ks][2] = packh2(sv[2 * ks + 1][0], sv[2 * ks + 1][1]);
                pa[ks][3] = packh2(sv[2 * ks + 1][2], sv[2 * ks + 1][3]);
            }

            // ---- O += P V  (V row-major via ldmatrix.trans) ----
#pragma unroll
            for (int ks = 0; ks < 4; ks++) {
#pragma unroll
                for (int np = 0; np < 4; np++) {
                    unsigned bf[4];
                    ldsm4t(bf, u_v + offBv + ks * (16 * HPAD * 2) + np * 32);
                    mma_f16(o[2 * np],     pa[ks], &bf[0]);
                    mma_f16(o[2 * np + 1], pa[ks], &bf[2]);
                }
            }

            // prefetch k-tile kt+2 into ring slot
            if (kt + 2 < nk) AKLOAD(kt + 2, (kt + 2) % 3);
            asm volatile("cp.async.commit_group;");
        }

        // ---- row-sum reduce across quad lanes, then epilogue ----
        l0 += __shfl_xor_sync(0xffffffffu, l0, 1);
        l0 += __shfl_xor_sync(0xffffffffu, l0, 2);
        l1 += __shfl_xor_sync(0xffffffffu, l1, 1);
        l1 += __shfl_xor_sync(0xffffffffu, l1, 2);

        const float inv0 = 1.0f / l0, inv1 = 1.0f / l1;
        __half* ob = g_oh + ((size_t)b * SS + (size_t)qt * 128 + warp * 16 + qr) * DD + h * DKK;
#pragma unroll
        for (int nt = 0; nt < 8; nt++) {
            int c0 = nt * 8 + 2 * ql;
            *(__half2*)&ob[c0] = __floats2half2_rn(o[nt][0] * inv0, o[nt][1] * inv0);
            *(__half2*)&ob[(size_t)8 * DD + c0] = __floats2half2_rn(o[nt][2] * inv1, o[nt][3] * inv1);
        }
        __syncthreads();
    }
#undef AKLOAD
}

// ---------------------------------------------------------------------------
extern "C" void kernel_launch(void* const* d_in, const int* in_sizes, int n_in,
                              void* d_out, int out_size) {
    const float* x  = (const float*)d_in[0];
    const float* wq = (const float*)d_in[1];
    const float* wk = (const float*)d_in[2];
    const float* wv = (const float*)d_in[3];
    const float* wo = (const float*)d_in[4];
    const int*   tp = (const int*)d_in[5];
    float* out = (float*)d_out;

    prep_all<<<TBLK + (NX4 + 4 * NW4) / 256, 256>>>(tp, x, wq, wk, wv, wo);

    const int GEMM_SMEM = 4 * GSTG;          // 81920 B
    cudaFuncSetAttribute(gemm_qkv, cudaFuncAttributeMaxDynamicSharedMemorySize, GEMM_SMEM);
    cudaFuncSetAttribute(gemm_out, cudaFuncAttributeMaxDynamicSharedMemorySize, GEMM_SMEM);

    gemm_qkv<<<dim3(24, (BB * SS) / 128), 256, GEMM_SMEM>>>();

    cudaFuncSetAttribute(attn_h, cudaFuncAttributeMaxDynamicSharedMemorySize, ATTN_SMEM_B);
    attn_h<<<dim3(SS / 256, HH, BB), 256, ATTN_SMEM_B>>>();

    gemm_out<<<dim3(DD / 128, (BB * SS) / 128), 256, GEMM_SMEM>>>(out);
}

// round 16
// speedup vs baseline: 1.0409x; 1.0040x over previous
#include <cuda_runtime.h>
#include <cuda_fp16.h>
#include <math.h>
#include <stdint.h>

#define BB 4
#define SS 2048
#define DD 1024
#define HH 16
#define DKK 64
#define NTOT (BB*SS*DD)

// ---------------------------------------------------------------------------
// Scratch (device globals — no allocations allowed)
// ---------------------------------------------------------------------------
__device__ float  g_cs[SS * 32];
__device__ float  g_sn[SS * 32];
__device__ __half g_xh[NTOT];
__device__ __half g_wh[4 * DD * DD];
__device__ __half g_qh[NTOT];
__device__ __half g_kh[NTOT];
__device__ __half g_vh[NTOT];
__device__ __half g_oh[NTOT];

// ---------------------------------------------------------------------------
// mma / ldmatrix / cp.async / griddepcontrol helpers
// ---------------------------------------------------------------------------
__device__ __forceinline__ void mma_f16(float* c, const unsigned* a, const unsigned* b) {
    asm volatile(
        "mma.sync.aligned.m16n8k16.row.col.f32.f16.f16.f32 "
        "{%0,%1,%2,%3},{%4,%5,%6,%7},{%8,%9},{%0,%1,%2,%3};\n"
        : "+f"(c[0]), "+f"(c[1]), "+f"(c[2]), "+f"(c[3])
        : "r"(a[0]), "r"(a[1]), "r"(a[2]), "r"(a[3]), "r"(b[0]), "r"(b[1]));
}
__device__ __forceinline__ void ldsm4(unsigned* r, uint32_t addr) {
    asm volatile("ldmatrix.sync.aligned.m8n8.x4.shared.b16 {%0,%1,%2,%3}, [%4];"
        : "=r"(r[0]), "=r"(r[1]), "=r"(r[2]), "=r"(r[3]) : "r"(addr));
}
__device__ __forceinline__ void ldsm4t(unsigned* r, uint32_t addr) {
    asm volatile("ldmatrix.sync.aligned.m8n8.x4.trans.shared.b16 {%0,%1,%2,%3}, [%4];"
        : "=r"(r[0]), "=r"(r[1]), "=r"(r[2]), "=r"(r[3]) : "r"(addr));
}
__device__ __forceinline__ void cp16(uint32_t dst, const void* src) {
    asm volatile("cp.async.cg.shared.global [%0], [%1], 16;" :: "r"(dst), "l"(src));
}
__device__ __forceinline__ uint32_t smem_u32(const void* p) {
    uint32_t a;
    asm("{ .reg .u64 t; cvta.to.shared.u64 t, %1; cvt.u32.u64 %0, t; }" : "=r"(a) : "l"(p));
    return a;
}
__device__ __forceinline__ unsigned packh2(float a, float b) {
    __half2 h = __floats2half2_rn(a, b);
    return *(unsigned*)&h;
}
__device__ __forceinline__ float ex2(float x) {
    float y;
    asm("ex2.approx.f32 %0, %1;" : "=f"(y) : "f"(x));
    return y;
}
__device__ __forceinline__ void gdc_launch() {
    asm volatile("griddepcontrol.launch_dependents;");
}
__device__ __forceinline__ void gdc_wait() {
    asm volatile("griddepcontrol.wait;" ::: "memory");
}

// ---------------------------------------------------------------------------
// Fused prep: RoPE table (blocks [0,256)) + fp32->fp16 conversion.
// ---------------------------------------------------------------------------
#define NX4 (NTOT/4)
#define NW4 ((DD*DD)/4)
#define TBLK 256
__global__ void prep_all(const int* __restrict__ tp,
                         const float* __restrict__ x,  const float* __restrict__ wq,
                         const float* __restrict__ wk, const float* __restrict__ wv,
                         const float* __restrict__ wo) {
    gdc_launch();
    if (blockIdx.x < TBLK) {
        int i = blockIdx.x * blockDim.x + threadIdx.x;
        int s = i >> 5, p = i & 31;
        float pos = (float)tp[s];
        float inv = (float)exp(-(double)p * 0.28782313662425572);
        float ang = pos * inv;
        float sn, cs;
        sincosf(ang, &sn, &cs);
        g_cs[i] = cs;
        g_sn[i] = sn;
        return;
    }
    int i = (blockIdx.x - TBLK) * blockDim.x + threadIdx.x;
    const float* src;
    __half* dst;
    int j;
    if (i < NX4) { src = x; dst = g_xh; j = i; }
    else {
        int r = i - NX4;
        int seg = r / NW4;
        j = r - seg * NW4;
        src = (seg == 0) ? wq : (seg == 1) ? wk : (seg == 2) ? wv : wo;
        dst = g_wh + (size_t)seg * DD * DD;
    }
    float4 v = ((const float4*)src)[j];
    ((__half2*)dst)[2 * j]     = __floats2half2_rn(v.x, v.y);
    ((__half2*)dst)[2 * j + 1] = __floats2half2_rn(v.z, v.w);
}

// ---------------------------------------------------------------------------
// GEMM mainloop: single barrier per k-stage. pdl_split=true defers A-operand
// loads until after griddepcontrol.wait (B loads overlap predecessor tail).
// ---------------------------------------------------------------------------
#define GSTG 20480
__device__ __forceinline__ void gemm_main(uint32_t smb, const __half* Ag,
                                          const __half* Bg, float acc[4][4][4],
                                          bool pdl_split) {
    const int t = threadIdx.x;
    const int lane = t & 31, warp = t >> 5;
    const int wm = (warp >> 2) * 64, wn = (warp & 3) * 32;
    const int chunk = t & 3, row0 = t >> 2;
    Ag += chunk * 8;
    Bg += chunk * 8;

    const uint32_t a_off = ((wm + (lane & 15)) * 40 + (lane >> 4) * 8) * 2;
    const int br = lane & 7, bg = lane >> 3;
    const uint32_t b_off = ((wn + br + (bg >> 1) * 8) * 40 + (bg & 1) * 8) * 2;

    if (pdl_split) {
        // B (weights) first — independent of the immediate predecessor
#pragma unroll
        for (int ps = 0; ps < 3; ps++) {
            uint32_t sb = smb + ps * GSTG;
            const __half* gb = Bg + ps * 32;
#pragma unroll
            for (int j = 0; j < 2; j++) {
                int row = row0 + j * 64;
                cp16(sb + 128 * 80 + row * 80 + chunk * 16, gb + (size_t)row * DD);
            }
        }
        gdc_wait();   // predecessor (attn) complete -> A (g_oh) valid
#pragma unroll
        for (int ps = 0; ps < 3; ps++) {
            uint32_t sb = smb + ps * GSTG;
            const __half* ga = Ag + ps * 32;
#pragma unroll
            for (int j = 0; j < 2; j++) {
                int row = row0 + j * 64;
                cp16(sb + row * 80 + chunk * 16, ga + (size_t)row * DD);
            }
            asm volatile("cp.async.commit_group;");
        }
    } else {
#pragma unroll
        for (int ps = 0; ps < 3; ps++) {
            uint32_t sb = smb + ps * GSTG;
            const __half* ga = Ag + ps * 32;
            const __half* gb = Bg + ps * 32;
#pragma unroll
            for (int j = 0; j < 2; j++) {
                int row = row0 + j * 64;
                cp16(sb + row * 80 + chunk * 16, ga + (size_t)row * DD);
                cp16(sb + 128 * 80 + row * 80 + chunk * 16, gb + (size_t)row * DD);
            }
            asm volatile("cp.async.commit_group;");
        }
    }

    for (int s = 0; s < 32; s++) {
        asm volatile("cp.async.wait_group 2;");
        __syncthreads();
        const uint32_t sA = smb + (s & 3) * GSTG;
        const uint32_t sB = sA + 128 * 80;
#pragma unroll
        for (int ks = 0; ks < 2; ks++) {
            unsigned af[4][4], bf[2][4];
#pragma unroll
            for (int mt = 0; mt < 4; mt++)
                ldsm4(af[mt], sA + a_off + mt * (16 * 80) + ks * 32);
#pragma unroll
            for (int np = 0; np < 2; np++)
                ldsm4(bf[np], sB + b_off + np * (16 * 80) + ks * 32);
#pragma unroll
            for (int mt = 0; mt < 4; mt++)
#pragma unroll
                for (int nt = 0; nt < 4; nt++)
                    mma_f16(acc[mt][nt], af[mt], &bf[nt >> 1][(nt & 1) * 2]);
        }
        if (s + 3 < 32) {
            uint32_t sb = smb + ((s + 3) & 3) * GSTG;
            const __half* ga = Ag + (s + 3) * 32;
            const __half* gb = Bg + (s + 3) * 32;
#pragma unroll
            for (int j = 0; j < 2; j++) {
                int row = row0 + j * 64;
                cp16(sb + row * 80 + chunk * 16, ga + (size_t)row * DD);
                cp16(sb + 128 * 80 + row * 80 + chunk * 16, gb + (size_t)row * DD);
            }
        }
        asm volatile("cp.async.commit_group;");
    }
}

// ---------------------------------------------------------------------------
// Fused QKV GEMM + RoPE epilogue. Q scale 0.125*log2(e).
// ---------------------------------------------------------------------------
#define QSCALE 0.1803368801111204f
__global__ __launch_bounds__(256) void gemm_qkv() {
    extern __shared__ __align__(128) char smem[];
    const uint32_t smb = smem_u32(smem);
    const int t = threadIdx.x;
    const int lane = t & 31, warp = t >> 5;
    const int qr = lane >> 2, ql = lane & 3;
    const int wm = (warp >> 2) * 64, wn = (warp & 3) * 32;
    const int w  = blockIdx.x >> 3;
    const int bn = (blockIdx.x & 7) * 128;
    const int bm = blockIdx.y * 128;

    gdc_launch();
    gdc_wait();   // prep complete (x/w conversions + rope table)

    float acc[4][4][4] = {};
    gemm_main(smb, g_xh + (size_t)bm * DD, g_wh + (size_t)w * DD * DD + (size_t)bn * DD,
              acc, false);

    const int r0 = bm + wm + qr;
    const int c0 = bn + wn + 2 * ql;
    if (w == 2) {
#pragma unroll
        for (int mt = 0; mt < 4; mt++)
#pragma unroll
            for (int nt = 0; nt < 4; nt++) {
                __half* vp = g_vh + (size_t)(r0 + mt * 16) * DD + c0 + nt * 8;
                *(__half2*)vp = __floats2half2_rn(acc[mt][nt][0], acc[mt][nt][1]);
                *(__half2*)(vp + 8 * DD) = __floats2half2_rn(acc[mt][nt][2], acc[mt][nt][3]);
            }
    } else {
        __half* dst = (w == 0) ? g_qh : g_kh;
        const float sc = (w == 0) ? QSCALE : 1.0f;
#pragma unroll
        for (int mt = 0; mt < 4; mt++) {
            int rA = r0 + mt * 16;
            int rB = rA + 8;
            int sA = rA & (SS - 1), sB = rB & (SS - 1);
#pragma unroll
            for (int nt = 0; nt < 4; nt++) {
                int cc = c0 + nt * 8;
                int p = (cc & 63) >> 1;
                float csA = g_cs[sA * 32 + p], snA = g_sn[sA * 32 + p];
                float csB = g_cs[sB * 32 + p], snB = g_sn[sB * 32 + p];
                float a0 = acc[mt][nt][0], a1 = acc[mt][nt][1];
                float b0 = acc[mt][nt][2], b1 = acc[mt][nt][3];
                __half* dp = dst + (size_t)rA * DD + cc;
                *(__half2*)dp = __floats2half2_rn((a0 * csA - a1 * snA) * sc,
                                                  (a0 * snA + a1 * csA) * sc);
                *(__half2*)(dp + 8 * DD) = __floats2half2_rn((b0 * csB - b1 * snB) * sc,
                                                             (b0 * snB + b1 * csB) * sc);
            }
        }
    }
}

// ---------------------------------------------------------------------------
// Output projection GEMM (PDL: B prefetch before wait)
// ---------------------------------------------------------------------------
__global__ __launch_bounds__(256) void gemm_out(float* __restrict__ C) {
    extern __shared__ __align__(128) char smem[];
    const uint32_t smb = smem_u32(smem);
    const int t = threadIdx.x;
    const int lane = t & 31, warp = t >> 5;
    const int qr = lane >> 2, ql = lane & 3;
    const int wm = (warp >> 2) * 64, wn = (warp & 3) * 32;
    const int bn = blockIdx.x * 128;
    const int bm = blockIdx.y * 128;

    gdc_launch();
    // NOTE: no wait yet — B (weights) loads are safe (prep transitively done);
    // gemm_main(pdl_split=true) waits before touching A = g_oh.
    float acc[4][4][4] = {};
    gemm_main(smb, g_oh + (size_t)bm * DD, g_wh + (size_t)3 * DD * DD + (size_t)bn * DD,
              acc, true);

    const int r0 = bm + wm + qr;
    const int c0 = bn + wn + 2 * ql;
#pragma unroll
    for (int mt = 0; mt < 4; mt++)
#pragma unroll
        for (int nt = 0; nt < 4; nt++) {
            float* cp = C + (size_t)(r0 + mt * 16) * DD + c0 + nt * 8;
            *(float2*)cp = make_float2(acc[mt][nt][0], acc[mt][nt][1]);
            *(float2*)(cp + 8 * DD) = make_float2(acc[mt][nt][2], acc[mt][nt][3]);
        }
}

// ---------------------------------------------------------------------------
// fp16 flash attention (exact R10/R15 configuration — measured optimum)
// ---------------------------------------------------------------------------
#define HPAD 72
#define QT_B  (0)
#define KT_B(s) (128 * HPAD * 2 + (s) * (2 * 64 * HPAD * 2))
#define VT_B(s) (KT_B(s) + 64 * HPAD * 2)
#define ATTN_SMEM_B (128 * HPAD * 2 + 6 * 64 * HPAD * 2)   // 73728

__global__ __launch_bounds__(256) void attn_h() {
    extern __shared__ __align__(16) __half smh[];
    const uint32_t u0 = smem_u32(smh);
    __half* Qs = smh;

    const int h = blockIdx.y, b = blockIdx.z;
    const int t = threadIdx.x;
    const int lane = t & 31, warp = t >> 5;
    const int qr = lane >> 2, ql = lane & 3;
    const int br = lane & 7, bg = lane >> 3;

    const uint32_t offA  = ((warp * 16 + (lane & 15)) * HPAD + (lane >> 4) * 8) * 2;
    const uint32_t offBk = ((br + (bg >> 1) * 8) * HPAD + (bg & 1) * 8) * 2;
    const uint32_t offBv = ((br + (bg & 1) * 8) * HPAD + (bg >> 1) * 8) * 2;

    gdc_launch();
    gdc_wait();   // gemm_qkv complete -> q/k/v valid

#define AKLOAD(kt_, buf_) do {                                                      \
        const __half* kb_ = g_kh + ((size_t)b * SS + (size_t)(kt_) * 64) * DD + h * DKK; \
        const __half* vb_ = g_vh + ((size_t)b * SS + (size_t)(kt_) * 64) * DD + h * DKK; \
        uint32_t kd_ = u0 + KT_B(buf_), vd_ = u0 + VT_B(buf_);                      \
        _Pragma("unroll")                                                           \
        for (int i_ = 0; i_ < 2; i_++) {                                            \
            int idx_ = t + i_ * 256;                                                \
            int r_ = idx_ >> 3, cb_ = (idx_ & 7) * 16;                              \
            cp16(kd_ + r_ * (HPAD * 2) + cb_, kb_ + (size_t)r_ * DD + (idx_ & 7) * 8); \
            cp16(vd_ + r_ * (HPAD * 2) + cb_, vb_ + (size_t)r_ * DD + (idx_ & 7) * 8); \
        }                                                                           \
    } while (0)

#pragma unroll
    for (int pass = 0; pass < 2; pass++) {
        const int qt = pass ? blockIdx.x : 15 - blockIdx.x;
        const int nk = 2 * qt + 2;

        const __half* qb = g_qh + ((size_t)b * SS + (size_t)qt * 128) * DD + h * DKK;
#pragma unroll
        for (int i = 0; i < 4; i++) {
            int idx = t + i * 256;
            int r = idx >> 3, c = (idx & 7) * 8;
            *(uint4*)&Qs[r * HPAD + c] = *(const uint4*)&qb[(size_t)r * DD + c];
        }

        float o[8][4] = {};
        float l0 = 0.0f, l1 = 0.0f;

        AKLOAD(0, 0);
        asm volatile("cp.async.commit_group;");
        AKLOAD(1, 1);
        asm volatile("cp.async.commit_group;");

        int buf = 0;
        for (int kt = 0; kt < nk; kt++) {
            asm volatile("cp.async.wait_group 1;");
            __syncthreads();

            const uint32_t u_k = u0 + KT_B(buf);
            const uint32_t u_v = u0 + VT_B(buf);
            buf = (buf == 2) ? 0 : buf + 1;

            float sv[8][4] = {};
#pragma unroll
            for (int ks = 0; ks < 4; ks++) {
                unsigned a[4];
                ldsm4(a, u0 + QT_B + offA + ks * 32);
#pragma unroll
                for (int np = 0; np < 4; np++) {
                    unsigned bf[4];
                    ldsm4(bf, u_k + offBk + np * (16 * HPAD * 2) + ks * 32);
                    mma_f16(sv[2 * np],     a, &bf[0]);
                    mma_f16(sv[2 * np + 1], a, &bf[2]);
                }
            }

            if (kt >= 2 * qt) {
                const int off = (kt - 2 * qt) * 64;
                const int r_lo = warp * 16 + qr - off, r_hi = r_lo + 8;
#pragma unroll
                for (int nt = 0; nt < 8; nt++) {
                    int c0 = nt * 8 + 2 * ql, c1 = c0 + 1;
                    if (c0 > r_lo) sv[nt][0] = -1e30f;
                    if (c1 > r_lo) sv[nt][1] = -1e30f;
                    if (c0 > r_hi) sv[nt][2] = -1e30f;
                    if (c1 > r_hi) sv[nt][3] = -1e30f;
                }
            }

            float rs0 = 0.0f, rs1 = 0.0f;
#pragma unroll
            for (int nt = 0; nt < 8; nt++) {
                sv[nt][0] = ex2(sv[nt][0]);
                sv[nt][1] = ex2(sv[nt][1]);
                sv[nt][2] = ex2(sv[nt][2]);
                sv[nt][3] = ex2(sv[nt][3]);
                rs0 += sv[nt][0] + sv[nt][1];
                rs1 += sv[nt][2] + sv[nt][3];
            }
            l0 += rs0;
            l1 += rs1;

            unsigned pa[4][4];
#pragma unroll
            for (int ks = 0; ks < 4; ks++) {
                pa[ks][0] = packh2(sv[2 * ks][0],     sv[2 * ks][1]);
                pa[ks][1] = packh2(sv[2 * ks][2],     sv[2 * ks][3]);
                pa[ks][2] = packh2(sv[2 * ks + 1][0], sv[2 * ks + 1][1]);
                pa[ks][3] = packh2(sv[2 * ks + 1][2], sv[2 * ks + 1][3]);
            }

#pragma unroll
            for (int ks = 0; ks < 4; ks++) {
#pragma unroll
                for (int np = 0; np < 4; np++) {
                    unsigned bf[4];
                    ldsm4t(bf, u_v + offBv + ks * (16 * HPAD * 2) + np * 32);
                    mma_f16(o[2 * np],     pa[ks], &bf[0]);
                    mma_f16(o[2 * np + 1], pa[ks], &bf[2]);
                }
            }

            if (kt + 2 < nk) AKLOAD(kt + 2, (kt + 2) % 3);
            asm volatile("cp.async.commit_group;");
        }

        l0 += __shfl_xor_sync(0xffffffffu, l0, 1);
        l0 += __shfl_xor_sync(0xffffffffu, l0, 2);
        l1 += __shfl_xor_sync(0xffffffffu, l1, 1);
        l1 += __shfl_xor_sync(0xffffffffu, l1, 2);

        const float inv0 = 1.0f / l0, inv1 = 1.0f / l1;
        __half* ob = g_oh + ((size_t)b * SS + (size_t)qt * 128 + warp * 16 + qr) * DD + h * DKK;
#pragma unroll
        for (int nt = 0; nt < 8; nt++) {
            int c0 = nt * 8 + 2 * ql;
            *(__half2*)&ob[c0] = __floats2half2_rn(o[nt][0] * inv0, o[nt][1] * inv0);
            *(__half2*)&ob[(size_t)8 * DD + c0] = __floats2half2_rn(o[nt][2] * inv1, o[nt][3] * inv1);
        }
        __syncthreads();
    }
#undef AKLOAD
}

// ---------------------------------------------------------------------------
extern "C" void kernel_launch(void* const* d_in, const int* in_sizes, int n_in,
                              void* d_out, int out_size) {
    const float* x  = (const float*)d_in[0];
    const float* wq = (const float*)d_in[1];
    const float* wk = (const float*)d_in[2];
    const float* wv = (const float*)d_in[3];
    const float* wo = (const float*)d_in[4];
    const int*   tp = (const int*)d_in[5];
    float* out = (float*)d_out;

    const int GEMM_SMEM = 4 * GSTG;          // 81920 B
    cudaFuncSetAttribute(gemm_qkv, cudaFuncAttributeMaxDynamicSharedMemorySize, GEMM_SMEM);
    cudaFuncSetAttribute(gemm_out, cudaFuncAttributeMaxDynamicSharedMemorySize, GEMM_SMEM);
    cudaFuncSetAttribute(attn_h,  cudaFuncAttributeMaxDynamicSharedMemorySize, ATTN_SMEM_B);

    prep_all<<<TBLK + (NX4 + 4 * NW4) / 256, 256>>>(tp, x, wq, wk, wv, wo);

    cudaLaunchAttribute at[1];
    at[0].id = cudaLaunchAttributeProgrammaticStreamSerialization;
    at[0].val.programmaticStreamSerializationAllowed = 1;

    cudaLaunchConfig_t cfg = {};
    cfg.attrs = at;
    cfg.numAttrs = 1;
    cfg.blockDim = dim3(256, 1, 1);

    cfg.gridDim = dim3(24, (BB * SS) / 128, 1);
    cfg.dynamicSmemBytes = GEMM_SMEM;
    cudaLaunchKernelEx(&cfg, gemm_qkv);

    cfg.gridDim = dim3(SS / 256, HH, BB);
    cfg.dynamicSmemBytes = ATTN_SMEM_B;
    cudaLaunchKernelEx(&cfg, attn_h);

    cfg.gridDim = dim3(DD / 128, (BB * SS) / 128, 1);
    cfg.dynamicSmemBytes = GEMM_SMEM;
    cudaLaunchKernelEx(&cfg, gemm_out, out);
}

// round 17
// speedup vs baseline: 1.1273x; 1.0830x over previous
#include <cuda_runtime.h>
#include <cuda_fp16.h>
#include <math.h>
#include <stdint.h>

#define BB 4
#define SS 2048
#define DD 1024
#define HH 16
#define DKK 64
#define NTOT (BB*SS*DD)

// ---------------------------------------------------------------------------
// Scratch (device globals — no allocations allowed)
// ---------------------------------------------------------------------------
__device__ float  g_cs[SS * 32];
__device__ float  g_sn[SS * 32];
__device__ __half g_xh[NTOT];
__device__ __half g_wh[4 * DD * DD];
__device__ __half g_qh[NTOT];
__device__ __half g_kh[NTOT];
__device__ __half g_vh[NTOT];
__device__ __half g_oh[NTOT];
__device__ int    g_cnt_qkv[BB];        // qkv blocks done per batch (target 384)
__device__ int    g_cnt_attn[BB * 16];  // attn h-blocks done per (b,qt) (target 16)

// ---------------------------------------------------------------------------
// mma / ldmatrix / cp.async / griddepcontrol helpers
// ---------------------------------------------------------------------------
__device__ __forceinline__ void mma_f16(float* c, const unsigned* a, const unsigned* b) {
    asm volatile(
        "mma.sync.aligned.m16n8k16.row.col.f32.f16.f16.f32 "
        "{%0,%1,%2,%3},{%4,%5,%6,%7},{%8,%9},{%0,%1,%2,%3};\n"
        : "+f"(c[0]), "+f"(c[1]), "+f"(c[2]), "+f"(c[3])
        : "r"(a[0]), "r"(a[1]), "r"(a[2]), "r"(a[3]), "r"(b[0]), "r"(b[1]));
}
__device__ __forceinline__ void ldsm4(unsigned* r, uint32_t addr) {
    asm volatile("ldmatrix.sync.aligned.m8n8.x4.shared.b16 {%0,%1,%2,%3}, [%4];"
        : "=r"(r[0]), "=r"(r[1]), "=r"(r[2]), "=r"(r[3]) : "r"(addr));
}
__device__ __forceinline__ void ldsm4t(unsigned* r, uint32_t addr) {
    asm volatile("ldmatrix.sync.aligned.m8n8.x4.trans.shared.b16 {%0,%1,%2,%3}, [%4];"
        : "=r"(r[0]), "=r"(r[1]), "=r"(r[2]), "=r"(r[3]) : "r"(addr));
}
__device__ __forceinline__ void cp16(uint32_t dst, const void* src) {
    asm volatile("cp.async.cg.shared.global [%0], [%1], 16;" :: "r"(dst), "l"(src));
}
__device__ __forceinline__ uint32_t smem_u32(const void* p) {
    uint32_t a;
    asm("{ .reg .u64 t; cvta.to.shared.u64 t, %1; cvt.u32.u64 %0, t; }" : "=r"(a) : "l"(p));
    return a;
}
__device__ __forceinline__ unsigned packh2(float a, float b) {
    __half2 h = __floats2half2_rn(a, b);
    return *(unsigned*)&h;
}
__device__ __forceinline__ float ex2(float x) {
    float y;
    asm("ex2.approx.f32 %0, %1;" : "=f"(y) : "f"(x));
    return y;
}
__device__ __forceinline__ void gdc_launch() {
    asm volatile("griddepcontrol.launch_dependents;");
}
__device__ __forceinline__ void gdc_wait() {
    asm volatile("griddepcontrol.wait;" ::: "memory");
}
// consumer spin: one thread polls, then block-wide publish
__device__ __forceinline__ void spin_wait(const int* cnt, int target) {
    if (threadIdx.x == 0) {
        while (*(volatile const int*)cnt < target) __nanosleep(128);
    }
    __syncthreads();
    __threadfence();
}
// producer signal: all stores done by all threads, then one add
__device__ __forceinline__ void signal(int* cnt) {
    __threadfence();
    __syncthreads();
    if (threadIdx.x == 0) atomicAdd(cnt, 1);
}

// ---------------------------------------------------------------------------
// Fused prep: counter zeroing + RoPE table (blocks [0,256)) + fp32->fp16.
// ---------------------------------------------------------------------------
#define NX4 (NTOT/4)
#define NW4 ((DD*DD)/4)
#define TBLK 256
__global__ void prep_all(const int* __restrict__ tp,
                         const float* __restrict__ x,  const float* __restrict__ wq,
                         const float* __restrict__ wk, const float* __restrict__ wv,
                         const float* __restrict__ wo) {
    if (blockIdx.x < TBLK) {
        if (blockIdx.x == 0 && threadIdx.x < BB + BB * 16) {
            if (threadIdx.x < BB) g_cnt_qkv[threadIdx.x] = 0;
            else                  g_cnt_attn[threadIdx.x - BB] = 0;
        }
        int i = blockIdx.x * blockDim.x + threadIdx.x;
        int s = i >> 5, p = i & 31;
        float pos = (float)tp[s];
        float inv = (float)exp(-(double)p * 0.28782313662425572);
        float ang = pos * inv;
        float sn, cs;
        sincosf(ang, &sn, &cs);
        g_cs[i] = cs;
        g_sn[i] = sn;
        return;
    }
    int i = (blockIdx.x - TBLK) * blockDim.x + threadIdx.x;
    const float* src;
    __half* dst;
    int j;
    if (i < NX4) { src = x; dst = g_xh; j = i; }
    else {
        int r = i - NX4;
        int seg = r / NW4;
        j = r - seg * NW4;
        src = (seg == 0) ? wq : (seg == 1) ? wk : (seg == 2) ? wv : wo;
        dst = g_wh + (size_t)seg * DD * DD;
    }
    float4 v = ((const float4*)src)[j];
    ((__half2*)dst)[2 * j]     = __floats2half2_rn(v.x, v.y);
    ((__half2*)dst)[2 * j + 1] = __floats2half2_rn(v.z, v.w);
}

// ---------------------------------------------------------------------------
// GEMM mainloop. If cnt != nullptr: prefetch B (weights) into all 3 stages
// first, spin until *cnt >= target, then start A loads.
// ---------------------------------------------------------------------------
#define GSTG 20480
__device__ __forceinline__ void gemm_main(uint32_t smb, const __half* Ag,
                                          const __half* Bg, float acc[4][4][4],
                                          const int* cnt, int target) {
    const int t = threadIdx.x;
    const int lane = t & 31, warp = t >> 5;
    const int wm = (warp >> 2) * 64, wn = (warp & 3) * 32;
    const int chunk = t & 3, row0 = t >> 2;
    Ag += chunk * 8;
    Bg += chunk * 8;

    const uint32_t a_off = ((wm + (lane & 15)) * 40 + (lane >> 4) * 8) * 2;
    const int br = lane & 7, bg = lane >> 3;
    const uint32_t b_off = ((wn + br + (bg >> 1) * 8) * 40 + (bg & 1) * 8) * 2;

    if (cnt) {
        // B (weights) first — independent of the attention producer
#pragma unroll
        for (int ps = 0; ps < 3; ps++) {
            uint32_t sb = smb + ps * GSTG;
            const __half* gb = Bg + ps * 32;
#pragma unroll
            for (int j = 0; j < 2; j++) {
                int row = row0 + j * 64;
                cp16(sb + 128 * 80 + row * 80 + chunk * 16, gb + (size_t)row * DD);
            }
        }
        spin_wait(cnt, target);     // A producer (attn tile) complete
#pragma unroll
        for (int ps = 0; ps < 3; ps++) {
            uint32_t sb = smb + ps * GSTG;
            const __half* ga = Ag + ps * 32;
#pragma unroll
            for (int j = 0; j < 2; j++) {
                int row = row0 + j * 64;
                cp16(sb + row * 80 + chunk * 16, ga + (size_t)row * DD);
            }
            asm volatile("cp.async.commit_group;");
        }
    } else {
#pragma unroll
        for (int ps = 0; ps < 3; ps++) {
            uint32_t sb = smb + ps * GSTG;
            const __half* ga = Ag + ps * 32;
            const __half* gb = Bg + ps * 32;
#pragma unroll
            for (int j = 0; j < 2; j++) {
                int row = row0 + j * 64;
                cp16(sb + row * 80 + chunk * 16, ga + (size_t)row * DD);
                cp16(sb + 128 * 80 + row * 80 + chunk * 16, gb + (size_t)row * DD);
            }
            asm volatile("cp.async.commit_group;");
        }
    }

    for (int s = 0; s < 32; s++) {
        asm volatile("cp.async.wait_group 2;");
        __syncthreads();
        const uint32_t sA = smb + (s & 3) * GSTG;
        const uint32_t sB = sA + 128 * 80;
#pragma unroll
        for (int ks = 0; ks < 2; ks++) {
            unsigned af[4][4], bf[2][4];
#pragma unroll
            for (int mt = 0; mt < 4; mt++)
                ldsm4(af[mt], sA + a_off + mt * (16 * 80) + ks * 32);
#pragma unroll
            for (int np = 0; np < 2; np++)
                ldsm4(bf[np], sB + b_off + np * (16 * 80) + ks * 32);
#pragma unroll
            for (int mt = 0; mt < 4; mt++)
#pragma unroll
                for (int nt = 0; nt < 4; nt++)
                    mma_f16(acc[mt][nt], af[mt], &bf[nt >> 1][(nt & 1) * 2]);
        }
        if (s + 3 < 32) {
            uint32_t sb = smb + ((s + 3) & 3) * GSTG;
            const __half* ga = Ag + (s + 3) * 32;
            const __half* gb = Bg + (s + 3) * 32;
#pragma unroll
            for (int j = 0; j < 2; j++) {
                int row = row0 + j * 64;
                cp16(sb + row * 80 + chunk * 16, ga + (size_t)row * DD);
                cp16(sb + 128 * 80 + row * 80 + chunk * 16, gb + (size_t)row * DD);
            }
        }
        asm volatile("cp.async.commit_group;");
    }
}

// ---------------------------------------------------------------------------
// Fused QKV GEMM + RoPE epilogue. Signals per-batch completion.
// ---------------------------------------------------------------------------
#define QSCALE 0.1803368801111204f
__global__ __launch_bounds__(256) void gemm_qkv() {
    extern __shared__ __align__(128) char smem[];
    const uint32_t smb = smem_u32(smem);
    const int t = threadIdx.x;
    const int lane = t & 31, warp = t >> 5;
    const int qr = lane >> 2, ql = lane & 3;
    const int wm = (warp >> 2) * 64, wn = (warp & 3) * 32;
    const int w  = blockIdx.x >> 3;
    const int bn = (blockIdx.x & 7) * 128;
    const int bm = blockIdx.y * 128;

    gdc_wait();      // prep complete (conversions, table, counter zeroing)
    gdc_launch();    // AFTER wait: attn CTAs exist only once prep is done

    float acc[4][4][4] = {};
    gemm_main(smb, g_xh + (size_t)bm * DD, g_wh + (size_t)w * DD * DD + (size_t)bn * DD,
              acc, nullptr, 0);

    const int r0 = bm + wm + qr;
    const int c0 = bn + wn + 2 * ql;
    if (w == 2) {
#pragma unroll
        for (int mt = 0; mt < 4; mt++)
#pragma unroll
            for (int nt = 0; nt < 4; nt++) {
                __half* vp = g_vh + (size_t)(r0 + mt * 16) * DD + c0 + nt * 8;
                *(__half2*)vp = __floats2half2_rn(acc[mt][nt][0], acc[mt][nt][1]);
                *(__half2*)(vp + 8 * DD) = __floats2half2_rn(acc[mt][nt][2], acc[mt][nt][3]);
            }
    } else {
        __half* dst = (w == 0) ? g_qh : g_kh;
        const float sc = (w == 0) ? QSCALE : 1.0f;
#pragma unroll
        for (int mt = 0; mt < 4; mt++) {
            int rA = r0 + mt * 16;
            int rB = rA + 8;
            int sA = rA & (SS - 1), sB = rB & (SS - 1);
#pragma unroll
            for (int nt = 0; nt < 4; nt++) {
                int cc = c0 + nt * 8;
                int p = (cc & 63) >> 1;
                float csA = g_cs[sA * 32 + p], snA = g_sn[sA * 32 + p];
                float csB = g_cs[sB * 32 + p], snB = g_sn[sB * 32 + p];
                float a0 = acc[mt][nt][0], a1 = acc[mt][nt][1];
                float b0 = acc[mt][nt][2], b1 = acc[mt][nt][3];
                __half* dp = dst + (size_t)rA * DD + cc;
                *(__half2*)dp = __floats2half2_rn((a0 * csA - a1 * snA) * sc,
                                                  (a0 * snA + a1 * csA) * sc);
                *(__half2*)(dp + 8 * DD) = __floats2half2_rn((b0 * csB - b1 * snB) * sc,
                                                             (b0 * snB + b1 * csB) * sc);
            }
        }
    }
    signal(&g_cnt_qkv[blockIdx.y >> 4]);
}

// ---------------------------------------------------------------------------
// Output projection GEMM: per-(b,qt) spin on attn counters; B prefetch first.
// ---------------------------------------------------------------------------
__global__ __launch_bounds__(256) void gemm_out(float* __restrict__ C) {
    extern __shared__ __align__(128) char smem[];
    const uint32_t smb = smem_u32(smem);
    const int t = threadIdx.x;
    const int lane = t & 31, warp = t >> 5;
    const int qr = lane >> 2, ql = lane & 3;
    const int wm = (warp >> 2) * 64, wn = (warp & 3) * 32;
    const int bn = blockIdx.x * 128;
    const int bm = blockIdx.y * 128;

    float acc[4][4][4] = {};
    gemm_main(smb, g_oh + (size_t)bm * DD, g_wh + (size_t)3 * DD * DD + (size_t)bn * DD,
              acc, &g_cnt_attn[blockIdx.y], 16);

    const int r0 = bm + wm + qr;
    const int c0 = bn + wn + 2 * ql;
#pragma unroll
    for (int mt = 0; mt < 4; mt++)
#pragma unroll
        for (int nt = 0; nt < 4; nt++) {
            float* cp = C + (size_t)(r0 + mt * 16) * DD + c0 + nt * 8;
            *(float2*)cp = make_float2(acc[mt][nt][0], acc[mt][nt][1]);
            *(float2*)(cp + 8 * DD) = make_float2(acc[mt][nt][2], acc[mt][nt][3]);
        }
}

// ---------------------------------------------------------------------------
// fp16 flash attention (R10/R15 config) + per-batch spin + per-tile signal.
// __launch_bounds__(256,2) pins regs <= 128 (2 CTA/SM guaranteed).
// ---------------------------------------------------------------------------
#define HPAD 72
#define QT_B  (0)
#define KT_B(s) (128 * HPAD * 2 + (s) * (2 * 64 * HPAD * 2))
#define VT_B(s) (KT_B(s) + 64 * HPAD * 2)
#define ATTN_SMEM_B (128 * HPAD * 2 + 6 * 64 * HPAD * 2)   // 73728

__global__ __launch_bounds__(256, 2) void attn_h() {
    extern __shared__ __align__(16) __half smh[];
    const uint32_t u0 = smem_u32(smh);
    __half* Qs = smh;

    const int h = blockIdx.y, b = blockIdx.z;
    const int t = threadIdx.x;
    const int lane = t & 31, warp = t >> 5;
    const int qr = lane >> 2, ql = lane & 3;
    const int br = lane & 7, bg = lane >> 3;

    const uint32_t offA  = ((warp * 16 + (lane & 15)) * HPAD + (lane >> 4) * 8) * 2;
    const uint32_t offBk = ((br + (bg >> 1) * 8) * HPAD + (bg & 1) * 8) * 2;
    const uint32_t offBv = ((br + (bg & 1) * 8) * HPAD + (bg >> 1) * 8) * 2;

    // wait until ALL qkv blocks of this batch have signaled
    spin_wait(&g_cnt_qkv[b], 384);
    gdc_launch();   // AFTER spin: gemm_out CTAs exist only once qkv is done

#define AKLOAD(kt_, buf_) do {                                                      \
        const __half* kb_ = g_kh + ((size_t)b * SS + (size_t)(kt_) * 64) * DD + h * DKK; \
        const __half* vb_ = g_vh + ((size_t)b * SS + (size_t)(kt_) * 64) * DD + h * DKK; \
        uint32_t kd_ = u0 + KT_B(buf_), vd_ = u0 + VT_B(buf_);                      \
        _Pragma("unroll")                                                           \
        for (int i_ = 0; i_ < 2; i_++) {                                            \
            int idx_ = t + i_ * 256;                                                \
            int r_ = idx_ >> 3, cb_ = (idx_ & 7) * 16;                              \
            cp16(kd_ + r_ * (HPAD * 2) + cb_, kb_ + (size_t)r_ * DD + (idx_ & 7) * 8); \
            cp16(vd_ + r_ * (HPAD * 2) + cb_, vb_ + (size_t)r_ * DD + (idx_ & 7) * 8); \
        }                                                                           \
    } while (0)

#pragma unroll
    for (int pass = 0; pass < 2; pass++) {
        const int qt = pass ? blockIdx.x : 15 - blockIdx.x;
        const int nk = 2 * qt + 2;

        const __half* qb = g_qh + ((size_t)b * SS + (size_t)qt * 128) * DD + h * DKK;
#pragma unroll
        for (int i = 0; i < 4; i++) {
            int idx = t + i * 256;
            int r = idx >> 3, c = (idx & 7) * 8;
            *(uint4*)&Qs[r * HPAD + c] = *(const uint4*)&qb[(size_t)r * DD + c];
        }

        float o[8][4] = {};
        float l0 = 0.0f, l1 = 0.0f;

        AKLOAD(0, 0);
        asm volatile("cp.async.commit_group;");
        AKLOAD(1, 1);
        asm volatile("cp.async.commit_group;");

        int buf = 0;
        for (int kt = 0; kt < nk; kt++) {
            asm volatile("cp.async.wait_group 1;");
            __syncthreads();

            const uint32_t u_k = u0 + KT_B(buf);
            const uint32_t u_v = u0 + VT_B(buf);
            buf = (buf == 2) ? 0 : buf + 1;

            float sv[8][4] = {};
#pragma unroll
            for (int ks = 0; ks < 4; ks++) {
                unsigned a[4];
                ldsm4(a, u0 + QT_B + offA + ks * 32);
#pragma unroll
                for (int np = 0; np < 4; np++) {
                    unsigned bf[4];
                    ldsm4(bf, u_k + offBk + np * (16 * HPAD * 2) + ks * 32);
                    mma_f16(sv[2 * np],     a, &bf[0]);
                    mma_f16(sv[2 * np + 1], a, &bf[2]);
                }
            }

            if (kt >= 2 * qt) {
                const int off = (kt - 2 * qt) * 64;
                const int r_lo = warp * 16 + qr - off, r_hi = r_lo + 8;
#pragma unroll
                for (int nt = 0; nt < 8; nt++) {
                    int c0 = nt * 8 + 2 * ql, c1 = c0 + 1;
                    if (c0 > r_lo) sv[nt][0] = -1e30f;
                    if (c1 > r_lo) sv[nt][1] = -1e30f;
                    if (c0 > r_hi) sv[nt][2] = -1e30f;
                    if (c1 > r_hi) sv[nt][3] = -1e30f;
                }
            }

            float rs0 = 0.0f, rs1 = 0.0f;
#pragma unroll
            for (int nt = 0; nt < 8; nt++) {
                sv[nt][0] = ex2(sv[nt][0]);
                sv[nt][1] = ex2(sv[nt][1]);
                sv[nt][2] = ex2(sv[nt][2]);
                sv[nt][3] = ex2(sv[nt][3]);
                rs0 += sv[nt][0] + sv[nt][1];
                rs1 += sv[nt][2] + sv[nt][3];
            }
            l0 += rs0;
            l1 += rs1;

            unsigned pa[4][4];
#pragma unroll
            for (int ks = 0; ks < 4; ks++) {
                pa[ks][0] = packh2(sv[2 * ks][0],     sv[2 * ks][1]);
                pa[ks][1] = packh2(sv[2 * ks][2],     sv[2 * ks][3]);
                pa[ks][2] = packh2(sv[2 * ks + 1][0], sv[2 * ks + 1][1]);
                pa[ks][3] = packh2(sv[2 * ks + 1][2], sv[2 * ks + 1][3]);
            }

#pragma unroll
            for (int ks = 0; ks < 4; ks++) {
#pragma unroll
                for (int np = 0; np < 4; np++) {
                    unsigned bf[4];
                    ldsm4t(bf, u_v + offBv + ks * (16 * HPAD * 2) + np * 32);
                    mma_f16(o[2 * np],     pa[ks], &bf[0]);
                    mma_f16(o[2 * np + 1], pa[ks], &bf[2]);
                }
            }

            if (kt + 2 < nk) AKLOAD(kt + 2, (kt + 2) % 3);
            asm volatile("cp.async.commit_group;");
        }

        l0 += __shfl_xor_sync(0xffffffffu, l0, 1);
        l0 += __shfl_xor_sync(0xffffffffu, l0, 2);
        l1 += __shfl_xor_sync(0xffffffffu, l1, 1);
        l1 += __shfl_xor_sync(0xffffffffu, l1, 2);

        const float inv0 = 1.0f / l0, inv1 = 1.0f / l1;
        __half* ob = g_oh + ((size_t)b * SS + (size_t)qt * 128 + warp * 16 + qr) * DD + h * DKK;
#pragma unroll
        for (int nt = 0; nt < 8; nt++) {
            int c0 = nt * 8 + 2 * ql;
            *(__half2*)&ob[c0] = __floats2half2_rn(o[nt][0] * inv0, o[nt][1] * inv0);
            *(__half2*)&ob[(size_t)8 * DD + c0] = __floats2half2_rn(o[nt][2] * inv1, o[nt][3] * inv1);
        }
        // signal this (b,qt) tile complete (fence + barrier + add); the
        // barrier also protects smem reuse across passes.
        signal(&g_cnt_attn[b * 16 + qt]);
    }
#undef AKLOAD
}

// ---------------------------------------------------------------------------
extern "C" void kernel_launch(void* const* d_in, const int* in_sizes, int n_in,
                              void* d_out, int out_size) {
    const float* x  = (const float*)d_in[0];
    const float* wq = (const float*)d_in[1];
    const float* wk = (const float*)d_in[2];
    const float* wv = (const float*)d_in[3];
    const float* wo = (const float*)d_in[4];
    const int*   tp = (const int*)d_in[5];
    float* out = (float*)d_out;

    const int GEMM_SMEM = 4 * GSTG;          // 81920 B
    cudaFuncSetAttribute(gemm_qkv, cudaFuncAttributeMaxDynamicSharedMemorySize, GEMM_SMEM);
    cudaFuncSetAttribute(gemm_out, cudaFuncAttributeMaxDynamicSharedMemorySize, GEMM_SMEM);
    cudaFuncSetAttribute(attn_h,  cudaFuncAttributeMaxDynamicSharedMemorySize, ATTN_SMEM_B);

    prep_all<<<TBLK + (NX4 + 4 * NW4) / 256, 256>>>(tp, x, wq, wk, wv, wo);

    cudaLaunchAttribute at[1];
    at[0].id = cudaLaunchAttributeProgrammaticStreamSerialization;
    at[0].val.programmaticStreamSerializationAllowed = 1;

    cudaLaunchConfig_t cfg = {};
    cfg.attrs = at;
    cfg.numAttrs = 1;
    cfg.blockDim = dim3(256, 1, 1);

    cfg.gridDim = dim3(24, (BB * SS) / 128, 1);
    cfg.dynamicSmemBytes = GEMM_SMEM;
    cudaLaunchKernelEx(&cfg, gemm_qkv);

    cfg.gridDim = dim3(SS / 256, HH, BB);
    cfg.dynamicSmemBytes = ATTN_SMEM_B;
    cudaLaunchKernelEx(&cfg, attn_h);

    cfg.gridDim = dim3(DD / 128, (BB * SS) / 128, 1);
    cfg.dynamicSmemBytes = GEMM_SMEM;
    cudaLaunchKernelEx(&cfg, gemm_out, out);
}